// round 15
// baseline (speedup 1.0000x reference)
#include <cuda_runtime.h>
#include <cuda_bf16.h>
#include <math.h>
#include <stdint.h>

// Problem constants
#define BATCH   4
#define N_DAY   2048
#define N_CELLS 8192
#define D_MICRO 11
#define D       256
#define TOPK    32
#define NCAND   48
#define CAP     512
#define STG     64          // staged candidate rows
#define STRIDE  257         // smem stage stride (bank-conflict-free)

#define ROWS_Q  (BATCH * N_DAY)    // 8192
#define ROWS_M  (BATCH * N_CELLS)  // 32768

// ---------------- scratch (__device__ globals, allowed) ----------------
__device__ float g_xmicro[ROWS_Q * D];                      // 8 MB
__device__ float g_q     [ROWS_Q * D];                      // 8 MB
__device__ float g_k     [ROWS_M * D];                      // 32 MB
__device__ float g_mctx  [ROWS_Q * D];                      // 8 MB
__device__ float g_w2    [D * D];                           // 256 KB
__device__ __nv_bfloat16 g_sbf[(size_t)BATCH * N_DAY * N_CELLS]; // 128 MB
__device__ __nv_bfloat16 g_qs[(size_t)ROWS_Q * D];          // 4 MB
__device__ __nv_bfloat16 g_ks[(size_t)ROWS_M * D];          // 16 MB

// ================= PTX helpers =================
__device__ __forceinline__ uint32_t smem_u32(const void* p) {
    uint32_t a;
    asm("{ .reg .u64 t; cvta.to.shared.u64 t, %1; cvt.u32.u64 %0, t; }" : "=r"(a) : "l"(p));
    return a;
}
__device__ __forceinline__ void cp16(uint32_t dst, const void* src) {
    asm volatile("cp.async.cg.shared.global [%0], [%1], 16;" :: "r"(dst), "l"(src));
}
#define CP_COMMIT() asm volatile("cp.async.commit_group;" ::: "memory")
#define CP_WAIT(N)  asm volatile("cp.async.wait_group %0;" :: "n"(N) : "memory")

__device__ __forceinline__ void ldsm_x4(uint32_t addr, uint32_t& r0, uint32_t& r1,
                                        uint32_t& r2, uint32_t& r3) {
    asm volatile("ldmatrix.sync.aligned.m8n8.x4.shared.b16 {%0,%1,%2,%3}, [%4];"
                 : "=r"(r0), "=r"(r1), "=r"(r2), "=r"(r3) : "r"(addr));
}
__device__ __forceinline__ void mma_bf16(float* d, const uint32_t* a, const uint32_t* b) {
    asm volatile(
        "mma.sync.aligned.m16n8k16.row.col.f32.bf16.bf16.f32 "
        "{%0,%1,%2,%3}, {%4,%5,%6,%7}, {%8,%9}, {%0,%1,%2,%3};"
        : "+f"(d[0]), "+f"(d[1]), "+f"(d[2]), "+f"(d[3])
        : "r"(a[0]), "r"(a[1]), "r"(a[2]), "r"(a[3]), "r"(b[0]), "r"(b[1]));
}

// swizzled smem offset for a (row, 16B-chunk) of a [rows x 32 bf16] tile
__device__ __forceinline__ uint32_t phys(int r, int c) {
    return ((uint32_t)(r >> 1) << 7) | ((uint32_t)(r & 1) << 6)
         | ((uint32_t)((c ^ ((r >> 1) & 3))) << 4);
}

// ---------------- micro projection: [8192,11] @ [11,256] + b ----------------
__global__ void __launch_bounds__(256) micro_proj_kernel(
    const float* __restrict__ micro, const float* __restrict__ w,
    const float* __restrict__ b, float* __restrict__ out)
{
    __shared__ float ws[D_MICRO * D];
    __shared__ float bs[D];
    __shared__ float ms[8][D_MICRO];
    int tid = threadIdx.x;
    for (int i = tid; i < D_MICRO * D; i += 256) ws[i] = w[i];
    bs[tid] = b[tid];
    int row0 = blockIdx.x * 8;
    for (int i = tid; i < 8 * D_MICRO; i += 256)
        ms[i / D_MICRO][i % D_MICRO] = micro[(size_t)row0 * D_MICRO + i];
    __syncthreads();
    #pragma unroll
    for (int r = 0; r < 8; r++) {
        float s = bs[tid];
        #pragma unroll
        for (int k = 0; k < D_MICRO; k++) s += ms[r][k] * ws[k * D + tid];
        out[(size_t)(row0 + r) * D + tid] = s;
    }
}

// ---------------- fused Q+K projection GEMM (bit-identical accumulation) ----------------
#define BM 128
#define BN 128
#define BKK 8
#define QBLKS (ROWS_Q / BM)   // 64

__global__ void __launch_bounds__(256) qk_proj_kernel(
    const float* __restrict__ Xm, const float* __restrict__ Mx,
    const float* __restrict__ Wq, const float* __restrict__ Wk,
    float* __restrict__ Qf, float* __restrict__ Kf,
    __nv_bfloat16* __restrict__ Qb, __nv_bfloat16* __restrict__ Kb)
{
    bool isQ = blockIdx.y < QBLKS;
    const float* A = isQ ? Xm : Mx;
    const float* B = isQ ? Wq : Wk;
    float* C       = isQ ? Qf : Kf;
    __nv_bfloat16* Cb = isQ ? Qb : Kb;
    int bm = (isQ ? blockIdx.y : (blockIdx.y - QBLKS)) * BM;
    int bn = blockIdx.x * BN;
    const int K = D, N = D;

    __shared__ float As[BKK][BM + 4];
    __shared__ float Bs[BKK][BN + 4];
    int tid = threadIdx.x;
    int arow = tid >> 1, ak = (tid & 1) * 4;
    int brow = tid >> 5, bc = (tid & 31) * 4;
    int tx = tid & 15, ty = tid >> 4;
    int tm = ty * 8, tn = tx * 8;

    float acc[8][8];
    #pragma unroll
    for (int i = 0; i < 8; i++)
        #pragma unroll
        for (int j = 0; j < 8; j++) acc[i][j] = 0.f;

    for (int k0 = 0; k0 < K; k0 += BKK) {
        float4 av = *(const float4*)(A + (size_t)(bm + arow) * K + k0 + ak);
        float4 bv = *(const float4*)(B + (size_t)(k0 + brow) * N + bn + bc);
        As[ak + 0][arow] = av.x; As[ak + 1][arow] = av.y;
        As[ak + 2][arow] = av.z; As[ak + 3][arow] = av.w;
        *(float4*)&Bs[brow][bc] = bv;
        __syncthreads();
        #pragma unroll
        for (int k = 0; k < BKK; k++) {
            float a[8], bfr[8];
            #pragma unroll
            for (int i = 0; i < 8; i++) a[i] = As[k][tm + i];
            #pragma unroll
            for (int j = 0; j < 8; j++) bfr[j] = Bs[k][tn + j];
            #pragma unroll
            for (int i = 0; i < 8; i++)
                #pragma unroll
                for (int j = 0; j < 8; j++) acc[i][j] = fmaf(a[i], bfr[j], acc[i][j]);
        }
        __syncthreads();
    }

    #pragma unroll
    for (int i = 0; i < 8; i++) {
        size_t base = (size_t)(bm + tm + i) * N + bn + tn;
        #pragma unroll
        for (int j = 0; j < 8; j += 4) {
            float4 v = make_float4(acc[i][j], acc[i][j + 1], acc[i][j + 2], acc[i][j + 3]);
            *(float4*)(C + base + j) = v;
            __nv_bfloat162 h0 = __floats2bfloat162_rn(v.x, v.y);
            __nv_bfloat162 h1 = __floats2bfloat162_rn(v.z, v.w);
            uint2 pk;
            pk.x = *(uint32_t*)&h0;
            pk.y = *(uint32_t*)&h1;
            *(uint2*)(Cb + base + j) = pk;
        }
    }
}

// ---------------- output GEMM: out = m_ctx @ W2 + x_micro + op_b ----------------
__global__ void __launch_bounds__(256) out_gemm_kernel(
    const float* __restrict__ A, const float* __restrict__ B,
    float* __restrict__ C, const float* __restrict__ addsrc,
    const float* __restrict__ bias)
{
    const int K = D, N = D;
    __shared__ float As[BKK][BM + 4];
    __shared__ float Bs[BKK][BN + 4];
    int tid = threadIdx.x;
    int bm = blockIdx.y * BM;
    int bn = blockIdx.x * BN;
    int arow = tid >> 1, ak = (tid & 1) * 4;
    int brow = tid >> 5, bc = (tid & 31) * 4;
    int tx = tid & 15, ty = tid >> 4;
    int tm = ty * 8, tn = tx * 8;

    float acc[8][8];
    #pragma unroll
    for (int i = 0; i < 8; i++)
        #pragma unroll
        for (int j = 0; j < 8; j++) acc[i][j] = 0.f;

    for (int k0 = 0; k0 < K; k0 += BKK) {
        float4 av = *(const float4*)(A + (size_t)(bm + arow) * K + k0 + ak);
        float4 bv = *(const float4*)(B + (size_t)(k0 + brow) * N + bn + bc);
        As[ak + 0][arow] = av.x; As[ak + 1][arow] = av.y;
        As[ak + 2][arow] = av.z; As[ak + 3][arow] = av.w;
        *(float4*)&Bs[brow][bc] = bv;
        __syncthreads();
        #pragma unroll
        for (int k = 0; k < BKK; k++) {
            float a[8], bfr[8];
            #pragma unroll
            for (int i = 0; i < 8; i++) a[i] = As[k][tm + i];
            #pragma unroll
            for (int j = 0; j < 8; j++) bfr[j] = Bs[k][tn + j];
            #pragma unroll
            for (int i = 0; i < 8; i++)
                #pragma unroll
                for (int j = 0; j < 8; j++) acc[i][j] = fmaf(a[i], bfr[j], acc[i][j]);
        }
        __syncthreads();
    }

    #pragma unroll
    for (int i = 0; i < 8; i++) {
        size_t base = (size_t)(bm + tm + i) * N + bn + tn;
        #pragma unroll
        for (int j = 0; j < 8; j += 4) {
            float4 v = make_float4(acc[i][j], acc[i][j + 1], acc[i][j + 2], acc[i][j + 3]);
            float4 s = *(const float4*)(addsrc + base + j);
            v.x += s.x; v.y += s.y; v.z += s.z; v.w += s.w;
            v.x += bias[bn + tn + j + 0]; v.y += bias[bn + tn + j + 1];
            v.z += bias[bn + tn + j + 2]; v.w += bias[bn + tn + j + 3];
            *(float4*)(C + base + j) = v;
        }
    }
}

// ---------------- small GEMM for W2 = wv @ op_w  (256x256x256) ----------------
__global__ void __launch_bounds__(256) small_gemm_kernel(
    const float* __restrict__ A, const float* __restrict__ B, float* __restrict__ C)
{
    __shared__ float ar[D];
    int r = blockIdx.x, tid = threadIdx.x;
    ar[tid] = A[r * D + tid];
    __syncthreads();
    float acc = 0.f;
    #pragma unroll 8
    for (int k = 0; k < D; k++) acc = fmaf(ar[k], B[k * D + tid], acc);
    C[r * D + tid] = acc;
}

// ---------------- scores via mma.sync bf16 (nomination only; bf16 output) ----------------
#define SBM 128
#define SBN 256
#define NSTEP 8    // 256/32
#define SMEM_MMA 49152

__global__ void __launch_bounds__(256, 1) scores_mma_kernel(
    const __nv_bfloat16* __restrict__ Qs, const __nv_bfloat16* __restrict__ Ks,
    __nv_bfloat16* __restrict__ S)
{
    extern __shared__ char smc[];
    uint32_t sb = smem_u32(smc);
    const uint32_t aoff[2] = { 0u, 24576u };
    const uint32_t boff[2] = { 8192u, 32768u };

    int tid = threadIdx.x, lane = tid & 31, wid = tid >> 5;
    int wm = wid & 1, wn = wid >> 1;          // 2 x 4 warps
    int z = blockIdx.z, bm = blockIdx.y * SBM, bn = blockIdx.x * SBN;
    const __nv_bfloat16* Az = Qs + (size_t)z * N_DAY * D;
    const __nv_bfloat16* Bz = Ks + (size_t)z * N_CELLS * D;

    float d[4][8][4];
    #pragma unroll
    for (int mt = 0; mt < 4; mt++)
        #pragma unroll
        for (int nt = 0; nt < 8; nt++)
            #pragma unroll
            for (int c = 0; c < 4; c++) d[mt][nt][c] = 0.f;

    int lr  = lane & 15;
    int lch = lane >> 4;

    auto load_stage = [&](int ks, int st) {
        int k0 = ks * 32;
        const __nv_bfloat16* Ag = Az + (size_t)bm * D + k0;
        const __nv_bfloat16* Bg = Bz + (size_t)bn * D + k0;
        #pragma unroll
        for (int j = 0; j < 2; j++) {
            int idx = tid + 256 * j;
            int r = idx >> 2, c = idx & 3;
            cp16(sb + aoff[st] + phys(r, c), Ag + (size_t)r * D + c * 8);
        }
        #pragma unroll
        for (int j = 0; j < 4; j++) {
            int idx = tid + 256 * j;
            int r = idx >> 2, c = idx & 3;
            cp16(sb + boff[st] + phys(r, c), Bg + (size_t)r * D + c * 8);
        }
    };

    load_stage(0, 0);
    CP_COMMIT();

    #pragma unroll 1
    for (int ks = 0; ks < NSTEP; ks++) {
        int st = ks & 1;
        if (ks < NSTEP - 1) { load_stage(ks + 1, st ^ 1); CP_COMMIT(); CP_WAIT(1); }
        else                { CP_WAIT(0); }
        __syncthreads();

        #pragma unroll
        for (int kk = 0; kk < 2; kk++) {
            uint32_t a[4][4];
            #pragma unroll
            for (int mt = 0; mt < 4; mt++) {
                int row = wm * 64 + mt * 16 + lr;
                int ch  = 2 * kk + lch;
                ldsm_x4(sb + aoff[st] + phys(row, ch), a[mt][0], a[mt][1], a[mt][2], a[mt][3]);
            }
            uint32_t b[8][2];
            #pragma unroll
            for (int gt = 0; gt < 4; gt++) {
                int row = wn * 64 + gt * 16 + lr;
                int ch  = 2 * kk + lch;
                uint32_t r0, r1, r2, r3;
                ldsm_x4(sb + boff[st] + phys(row, ch), r0, r1, r2, r3);
                b[2 * gt][0] = r0; b[2 * gt][1] = r2;
                b[2 * gt + 1][0] = r1; b[2 * gt + 1][1] = r3;
            }
            #pragma unroll
            for (int mt = 0; mt < 4; mt++)
                #pragma unroll
                for (int nt = 0; nt < 8; nt++)
                    mma_bf16(d[mt][nt], a[mt], b[nt]);
        }
        __syncthreads();
    }

    // Epilogue: stage 64-row half-tiles in smem (conflict-free), write coalesced 16B.
    const float scale = 0.0625f;
    __nv_bfloat16* Sz = S + (size_t)z * N_DAY * N_CELLS;
    uint32_t* su = (uint32_t*)smc;   // [64][132] uint32 = 33792 B
    #pragma unroll
    for (int p = 0; p < 2; p++) {
        if (wm == p) {
            #pragma unroll
            for (int mt = 0; mt < 4; mt++) {
                #pragma unroll
                for (int nt = 0; nt < 8; nt++) {
                    int r0 = mt * 16 + (lane >> 2);
                    int cu = wn * 32 + nt * 4 + (lane & 3);
                    __nv_bfloat162 v0 = __floats2bfloat162_rn(d[mt][nt][0] * scale, d[mt][nt][1] * scale);
                    __nv_bfloat162 v1 = __floats2bfloat162_rn(d[mt][nt][2] * scale, d[mt][nt][3] * scale);
                    su[r0 * 132 + cu]       = *(uint32_t*)&v0;
                    su[(r0 + 8) * 132 + cu] = *(uint32_t*)&v1;
                }
            }
        }
        __syncthreads();
        #pragma unroll
        for (int it = 0; it < 8; it++) {
            int idx = it * 256 + tid;
            int r = idx >> 5, q = idx & 31;
            uint4 v = *(uint4*)&su[r * 132 + q * 4];
            *(uint4*)(Sz + (size_t)(bm + p * 64 + r) * N_CELLS + bn + q * 8) = v;
        }
        __syncthreads();
    }
}

// ---------------- fused top-k + context (smem-staged rescore) ----------------
__global__ void __launch_bounds__(256) topk_ctx_kernel(
    const __nv_bfloat16* __restrict__ scores, const float* __restrict__ Qf,
    const float* __restrict__ Kf, const float* __restrict__ Mx,
    float* __restrict__ attn, float* __restrict__ idxo, float* __restrict__ ctx)
{
    extern __shared__ float kstage[];        // [STG][STRIDE] floats, 65792 B
    __shared__ float qrow[D];
    __shared__ int   red[8];
    __shared__ int   sLo, sHi, sC;
    __shared__ int   buf[CAP];
    __shared__ float rv[CAP];
    __shared__ float vals[TOPK];
    __shared__ int   inds[TOPK];
    __shared__ float aw[TOPK];

    int row = blockIdx.x;
    int b = row >> 11;
    int tid = threadIdx.x;
    int lane = tid & 31, wid = tid >> 5;
    const __nv_bfloat16* sp = scores + (size_t)row * N_CELLS;

    qrow[tid] = Qf[(size_t)row * D + tid];
    if (tid == 0) { sLo = 0; sHi = 65536; sC = 0; }

    // load 32 bf16 scores per thread; convert in-register to packed monotonic 16-bit keys
    uint32_t kp[16];
    #pragma unroll
    for (int it = 0; it < 4; it++) {
        uint4 p = ((const uint4*)sp)[it * 256 + tid];
        uint32_t ww[4] = { p.x, p.y, p.z, p.w };
        #pragma unroll
        for (int h = 0; h < 4; h++) {
            uint32_t v = ww[h];
            uint32_t m = ((v >> 15) & 0x00010001u) * 0xFFFFu;
            kp[it * 4 + h] = v ^ (m | 0x80008000u);
        }
    }
    __syncthreads();

    // binary search: largest T with count(key >= T) >= NCAND
    int lo = 0, hi = 65536;
    #pragma unroll 1
    for (int iter = 0; iter < 16; iter++) {
        uint32_t T = (uint32_t)((lo + hi) >> 1);
        int cnt = 0;
        #pragma unroll
        for (int r = 0; r < 16; r++) {
            cnt += ((kp[r] & 0xFFFFu) >= T);
            cnt += ((kp[r] >> 16) >= T);
        }
        #pragma unroll
        for (int off = 16; off; off >>= 1) cnt += __shfl_xor_sync(0xffffffffu, cnt, off);
        if (lane == 0) red[wid] = cnt;
        __syncthreads();
        if (tid == 0) {
            int c = 0;
            #pragma unroll
            for (int w = 0; w < 8; w++) c += red[w];
            if (c >= NCAND) sLo = (int)T; else sHi = (int)T;
        }
        __syncthreads();
        lo = sLo; hi = sHi;
    }
    uint32_t Tstar = (uint32_t)lo;

    // collection: ballot-compacted indices with key >= Tstar
    #pragma unroll
    for (int it = 0; it < 4; it++) {
        int base = (it * 256 + tid) * 8;
        #pragma unroll
        for (int h = 0; h < 4; h++) {
            uint32_t k2 = kp[it * 4 + h];
            #pragma unroll
            for (int s = 0; s < 2; s++) {
                uint32_t key = (s == 0) ? (k2 & 0xFFFFu) : (k2 >> 16);
                bool hit = key >= Tstar;
                uint32_t bal = __ballot_sync(0xffffffffu, hit);
                if (bal) {
                    int ldr = (int)(__ffs(bal) - 1);
                    int wbase = 0;
                    if (lane == ldr) wbase = atomicAdd(&sC, __popc(bal));
                    wbase = __shfl_sync(0xffffffffu, wbase, ldr);
                    if (hit) {
                        int pos = wbase + __popc(bal & ((1u << lane) - 1u));
                        if (pos < CAP) buf[pos] = base + h * 2 + s;
                    }
                }
            }
        }
    }
    __syncthreads();
    int C = sC < CAP ? sC : CAP;
    int Cs = C < STG ? C : STG;

    // stage candidate K rows into smem, coalesced (exact copies)
    const float* Kb = Kf + (size_t)b * N_CELLS * D;
    for (int i = 0; i < Cs; i++) {
        kstage[i * STRIDE + tid] = Kb[(size_t)buf[i] * D + tid];
    }
    __syncthreads();

    // fp32 rescore: serial k=0..255 fmaf chain (identical order; staged values are exact copies)
    for (int i = tid; i < C; i += 256) {
        float s = 0.f;
        if (i < STG) {
            const float* kr = &kstage[i * STRIDE];
            #pragma unroll 8
            for (int k = 0; k < D; k++) s = fmaf(qrow[k], kr[k], s);
        } else {
            const float* kr = Kb + (size_t)buf[i] * D;
            #pragma unroll 8
            for (int k = 0; k < D; k++) s = fmaf(qrow[k], kr[k], s);
        }
        rv[i] = s * 0.0625f;
    }
    __syncthreads();

    // warp 0: select top-32 by (value desc, index asc), softmax, write
    if (tid < 32) {
        for (int it = 0; it < TOPK; it++) {
            float v = -INFINITY; int ci = 1 << 30; int slot = 0;
            for (int j = tid; j < C; j += 32) {
                float x = rv[j]; int cj = buf[j];
                if (x > v || (x == v && cj < ci)) { v = x; ci = cj; slot = j; }
            }
            #pragma unroll
            for (int off = 16; off; off >>= 1) {
                float ov = __shfl_down_sync(0xffffffffu, v, off);
                int   oc = __shfl_down_sync(0xffffffffu, ci, off);
                int   os = __shfl_down_sync(0xffffffffu, slot, off);
                if (ov > v || (ov == v && oc < ci)) { v = ov; ci = oc; slot = os; }
            }
            v    = __shfl_sync(0xffffffffu, v, 0);
            ci   = __shfl_sync(0xffffffffu, ci, 0);
            slot = __shfl_sync(0xffffffffu, slot, 0);
            if (tid == 0) { vals[it] = v; inds[it] = ci; rv[slot] = -INFINITY; }
            __syncwarp();
        }
        float m = vals[0];
        float e = expf(vals[tid] - m);
        float s = e;
        #pragma unroll
        for (int off = 16; off; off >>= 1) s += __shfl_xor_sync(0xffffffffu, s, off);
        float w = e / s;
        aw[tid] = w;
        attn[(size_t)row * TOPK + tid] = w;
        idxo[(size_t)row * TOPK + tid] = (float)inds[tid];
    }
    __syncthreads();

    // fused context: m_ctx[row,:] = sum_k aw[k] * macro[b, inds[k], :]  (coalesced)
    {
        const float* Mb = Mx + (size_t)b * N_CELLS * D;
        float acc = 0.f;
        #pragma unroll 8
        for (int k = 0; k < TOPK; k++)
            acc = fmaf(aw[k], Mb[(size_t)inds[k] * D + tid], acc);
        ctx[(size_t)row * D + tid] = acc;
    }
}

// ---------------- launch ----------------
extern "C" void kernel_launch(void* const* d_in, const int* in_sizes, int n_in,
                              void* d_out, int out_size)
{
    const float* micro = (const float*)d_in[0];
    const float* macro = (const float*)d_in[1];
    const float* mp_w  = (const float*)d_in[2];
    const float* mp_b  = (const float*)d_in[3];
    const float* wq    = (const float*)d_in[4];
    const float* wk    = (const float*)d_in[5];
    const float* wv    = (const float*)d_in[6];
    const float* op_w  = (const float*)d_in[7];
    const float* op_b  = (const float*)d_in[8];

    float* out  = (float*)d_out;
    float* attn = out + (size_t)ROWS_Q * D;
    float* idxo = attn + (size_t)ROWS_Q * TOPK;

    float *p_xm, *p_q, *p_k, *p_mc, *p_w2;
    __nv_bfloat16 *p_qs, *p_ks, *p_s;
    cudaGetSymbolAddress((void**)&p_xm, g_xmicro);
    cudaGetSymbolAddress((void**)&p_q,  g_q);
    cudaGetSymbolAddress((void**)&p_k,  g_k);
    cudaGetSymbolAddress((void**)&p_mc, g_mctx);
    cudaGetSymbolAddress((void**)&p_w2, g_w2);
    cudaGetSymbolAddress((void**)&p_qs, g_qs);
    cudaGetSymbolAddress((void**)&p_ks, g_ks);
    cudaGetSymbolAddress((void**)&p_s,  g_sbf);

    cudaFuncSetAttribute(scores_mma_kernel,
                         cudaFuncAttributeMaxDynamicSharedMemorySize, SMEM_MMA);
    const int SMEM_TOPK = STG * STRIDE * 4;   // 65792
    cudaFuncSetAttribute(topk_ctx_kernel,
                         cudaFuncAttributeMaxDynamicSharedMemorySize, SMEM_TOPK);

    // 0. x_micro = micro @ mp_w + mp_b
    micro_proj_kernel<<<ROWS_Q / 8, 256>>>(micro, mp_w, mp_b, p_xm);

    // 1. fused Q + K projections (fp32 + bf16 shadows)
    qk_proj_kernel<<<dim3(D / BN, QBLKS + ROWS_M / BM), 256>>>(
        p_xm, macro, wq, wk, p_q, p_k, p_qs, p_ks);

    // 2. approx scores = scale * Qb @ Kb^T  (tensor cores)
    scores_mma_kernel<<<dim3(N_CELLS / SBN, N_DAY / SBM, BATCH), 256, SMEM_MMA>>>(p_qs, p_ks, p_s);

    // 3. top-k + context, smem-staged rescore  [ncu capture slot]
    topk_ctx_kernel<<<ROWS_Q, 256, SMEM_TOPK>>>(p_s, p_q, p_k, macro, attn, idxo, p_mc);

    // 4. W2 = wv @ op_w
    small_gemm_kernel<<<D, 256>>>(wv, op_w, p_w2);

    // 5. x_conditioned = x_micro + m_ctx @ W2 + op_b
    out_gemm_kernel<<<dim3(D / BN, ROWS_Q / BM), 256>>>(p_mc, p_w2, out, p_xm, op_b);

    (void)in_sizes; (void)n_in; (void)out_size;
}

// round 16
// speedup vs baseline: 1.2613x; 1.2613x over previous
#include <cuda_runtime.h>
#include <cuda_bf16.h>
#include <math.h>
#include <stdint.h>

// Problem constants
#define BATCH   4
#define N_DAY   2048
#define N_CELLS 8192
#define D_MICRO 11
#define D       256
#define TOPK    32
#define NCAND   48
#define CAP     512

#define ROWS_Q  (BATCH * N_DAY)    // 8192
#define ROWS_M  (BATCH * N_CELLS)  // 32768

// ---------------- scratch (__device__ globals, allowed) ----------------
__device__ float g_xmicro[ROWS_Q * D];                      // 8 MB
__device__ float g_q     [ROWS_Q * D];                      // 8 MB
__device__ float g_k     [ROWS_M * D];                      // 32 MB
__device__ float g_mctx  [ROWS_Q * D];                      // 8 MB
__device__ float g_w2    [D * D];                           // 256 KB
__device__ __nv_bfloat16 g_sbf[(size_t)BATCH * N_DAY * N_CELLS]; // 128 MB
__device__ __nv_bfloat16 g_qs[(size_t)ROWS_Q * D];          // 4 MB
__device__ __nv_bfloat16 g_ks[(size_t)ROWS_M * D];          // 16 MB

// ================= PTX helpers =================
__device__ __forceinline__ uint32_t smem_u32(const void* p) {
    uint32_t a;
    asm("{ .reg .u64 t; cvta.to.shared.u64 t, %1; cvt.u32.u64 %0, t; }" : "=r"(a) : "l"(p));
    return a;
}
__device__ __forceinline__ void cp16(uint32_t dst, const void* src) {
    asm volatile("cp.async.cg.shared.global [%0], [%1], 16;" :: "r"(dst), "l"(src));
}
#define CP_COMMIT() asm volatile("cp.async.commit_group;" ::: "memory")
#define CP_WAIT(N)  asm volatile("cp.async.wait_group %0;" :: "n"(N) : "memory")

__device__ __forceinline__ void ldsm_x4(uint32_t addr, uint32_t& r0, uint32_t& r1,
                                        uint32_t& r2, uint32_t& r3) {
    asm volatile("ldmatrix.sync.aligned.m8n8.x4.shared.b16 {%0,%1,%2,%3}, [%4];"
                 : "=r"(r0), "=r"(r1), "=r"(r2), "=r"(r3) : "r"(addr));
}
__device__ __forceinline__ void mma_bf16(float* d, const uint32_t* a, const uint32_t* b) {
    asm volatile(
        "mma.sync.aligned.m16n8k16.row.col.f32.bf16.bf16.f32 "
        "{%0,%1,%2,%3}, {%4,%5,%6,%7}, {%8,%9}, {%0,%1,%2,%3};"
        : "+f"(d[0]), "+f"(d[1]), "+f"(d[2]), "+f"(d[3])
        : "r"(a[0]), "r"(a[1]), "r"(a[2]), "r"(a[3]), "r"(b[0]), "r"(b[1]));
}

// swizzled smem offset for a (row, 16B-chunk) of a [rows x 32 bf16] tile
__device__ __forceinline__ uint32_t phys(int r, int c) {
    return ((uint32_t)(r >> 1) << 7) | ((uint32_t)(r & 1) << 6)
         | ((uint32_t)((c ^ ((r >> 1) & 3))) << 4);
}

// ---------------- micro projection: [8192,11] @ [11,256] + b ----------------
__global__ void __launch_bounds__(256) micro_proj_kernel(
    const float* __restrict__ micro, const float* __restrict__ w,
    const float* __restrict__ b, float* __restrict__ out)
{
    __shared__ float ws[D_MICRO * D];
    __shared__ float bs[D];
    __shared__ float ms[8][D_MICRO];
    int tid = threadIdx.x;
    for (int i = tid; i < D_MICRO * D; i += 256) ws[i] = w[i];
    bs[tid] = b[tid];
    int row0 = blockIdx.x * 8;
    for (int i = tid; i < 8 * D_MICRO; i += 256)
        ms[i / D_MICRO][i % D_MICRO] = micro[(size_t)row0 * D_MICRO + i];
    __syncthreads();
    #pragma unroll
    for (int r = 0; r < 8; r++) {
        float s = bs[tid];
        #pragma unroll
        for (int k = 0; k < D_MICRO; k++) s += ms[r][k] * ws[k * D + tid];
        out[(size_t)(row0 + r) * D + tid] = s;
    }
}

// ---------------- fused Q+K projection GEMM (bit-identical accumulation) ----------------
#define BM 128
#define BN 128
#define BKK 8
#define QBLKS (ROWS_Q / BM)   // 64

__global__ void __launch_bounds__(256) qk_proj_kernel(
    const float* __restrict__ Xm, const float* __restrict__ Mx,
    const float* __restrict__ Wq, const float* __restrict__ Wk,
    float* __restrict__ Qf, float* __restrict__ Kf,
    __nv_bfloat16* __restrict__ Qb, __nv_bfloat16* __restrict__ Kb)
{
    bool isQ = blockIdx.y < QBLKS;
    const float* A = isQ ? Xm : Mx;
    const float* B = isQ ? Wq : Wk;
    float* C       = isQ ? Qf : Kf;
    __nv_bfloat16* Cb = isQ ? Qb : Kb;
    int bm = (isQ ? blockIdx.y : (blockIdx.y - QBLKS)) * BM;
    int bn = blockIdx.x * BN;
    const int K = D, N = D;

    __shared__ float As[BKK][BM + 4];
    __shared__ float Bs[BKK][BN + 4];
    int tid = threadIdx.x;
    int arow = tid >> 1, ak = (tid & 1) * 4;
    int brow = tid >> 5, bc = (tid & 31) * 4;
    int tx = tid & 15, ty = tid >> 4;
    int tm = ty * 8, tn = tx * 8;

    float acc[8][8];
    #pragma unroll
    for (int i = 0; i < 8; i++)
        #pragma unroll
        for (int j = 0; j < 8; j++) acc[i][j] = 0.f;

    for (int k0 = 0; k0 < K; k0 += BKK) {
        float4 av = *(const float4*)(A + (size_t)(bm + arow) * K + k0 + ak);
        float4 bv = *(const float4*)(B + (size_t)(k0 + brow) * N + bn + bc);
        As[ak + 0][arow] = av.x; As[ak + 1][arow] = av.y;
        As[ak + 2][arow] = av.z; As[ak + 3][arow] = av.w;
        *(float4*)&Bs[brow][bc] = bv;
        __syncthreads();
        #pragma unroll
        for (int k = 0; k < BKK; k++) {
            float a[8], bfr[8];
            #pragma unroll
            for (int i = 0; i < 8; i++) a[i] = As[k][tm + i];
            #pragma unroll
            for (int j = 0; j < 8; j++) bfr[j] = Bs[k][tn + j];
            #pragma unroll
            for (int i = 0; i < 8; i++)
                #pragma unroll
                for (int j = 0; j < 8; j++) acc[i][j] = fmaf(a[i], bfr[j], acc[i][j]);
        }
        __syncthreads();
    }

    #pragma unroll
    for (int i = 0; i < 8; i++) {
        size_t base = (size_t)(bm + tm + i) * N + bn + tn;
        #pragma unroll
        for (int j = 0; j < 8; j += 4) {
            float4 v = make_float4(acc[i][j], acc[i][j + 1], acc[i][j + 2], acc[i][j + 3]);
            *(float4*)(C + base + j) = v;
            __nv_bfloat162 h0 = __floats2bfloat162_rn(v.x, v.y);
            __nv_bfloat162 h1 = __floats2bfloat162_rn(v.z, v.w);
            uint2 pk;
            pk.x = *(uint32_t*)&h0;
            pk.y = *(uint32_t*)&h1;
            *(uint2*)(Cb + base + j) = pk;
        }
    }
}

// ---------------- output GEMM: out = m_ctx @ W2 + x_micro + op_b ----------------
__global__ void __launch_bounds__(256) out_gemm_kernel(
    const float* __restrict__ A, const float* __restrict__ B,
    float* __restrict__ C, const float* __restrict__ addsrc,
    const float* __restrict__ bias)
{
    const int K = D, N = D;
    __shared__ float As[BKK][BM + 4];
    __shared__ float Bs[BKK][BN + 4];
    int tid = threadIdx.x;
    int bm = blockIdx.y * BM;
    int bn = blockIdx.x * BN;
    int arow = tid >> 1, ak = (tid & 1) * 4;
    int brow = tid >> 5, bc = (tid & 31) * 4;
    int tx = tid & 15, ty = tid >> 4;
    int tm = ty * 8, tn = tx * 8;

    float acc[8][8];
    #pragma unroll
    for (int i = 0; i < 8; i++)
        #pragma unroll
        for (int j = 0; j < 8; j++) acc[i][j] = 0.f;

    for (int k0 = 0; k0 < K; k0 += BKK) {
        float4 av = *(const float4*)(A + (size_t)(bm + arow) * K + k0 + ak);
        float4 bv = *(const float4*)(B + (size_t)(k0 + brow) * N + bn + bc);
        As[ak + 0][arow] = av.x; As[ak + 1][arow] = av.y;
        As[ak + 2][arow] = av.z; As[ak + 3][arow] = av.w;
        *(float4*)&Bs[brow][bc] = bv;
        __syncthreads();
        #pragma unroll
        for (int k = 0; k < BKK; k++) {
            float a[8], bfr[8];
            #pragma unroll
            for (int i = 0; i < 8; i++) a[i] = As[k][tm + i];
            #pragma unroll
            for (int j = 0; j < 8; j++) bfr[j] = Bs[k][tn + j];
            #pragma unroll
            for (int i = 0; i < 8; i++)
                #pragma unroll
                for (int j = 0; j < 8; j++) acc[i][j] = fmaf(a[i], bfr[j], acc[i][j]);
        }
        __syncthreads();
    }

    #pragma unroll
    for (int i = 0; i < 8; i++) {
        size_t base = (size_t)(bm + tm + i) * N + bn + tn;
        #pragma unroll
        for (int j = 0; j < 8; j += 4) {
            float4 v = make_float4(acc[i][j], acc[i][j + 1], acc[i][j + 2], acc[i][j + 3]);
            float4 s = *(const float4*)(addsrc + base + j);
            v.x += s.x; v.y += s.y; v.z += s.z; v.w += s.w;
            v.x += bias[bn + tn + j + 0]; v.y += bias[bn + tn + j + 1];
            v.z += bias[bn + tn + j + 2]; v.w += bias[bn + tn + j + 3];
            *(float4*)(C + base + j) = v;
        }
    }
}

// ---------------- small GEMM for W2 = wv @ op_w  (256x256x256) ----------------
__global__ void __launch_bounds__(256) small_gemm_kernel(
    const float* __restrict__ A, const float* __restrict__ B, float* __restrict__ C)
{
    __shared__ float ar[D];
    int r = blockIdx.x, tid = threadIdx.x;
    ar[tid] = A[r * D + tid];
    __syncthreads();
    float acc = 0.f;
    #pragma unroll 8
    for (int k = 0; k < D; k++) acc = fmaf(ar[k], B[k * D + tid], acc);
    C[r * D + tid] = acc;
}

// ---------------- scores via mma.sync bf16 (nomination only; bf16 output) ----------------
#define SBM 128
#define SBN 256
#define NSTEP 8    // 256/32
#define SMEM_MMA 49152

__global__ void __launch_bounds__(256, 1) scores_mma_kernel(
    const __nv_bfloat16* __restrict__ Qs, const __nv_bfloat16* __restrict__ Ks,
    __nv_bfloat16* __restrict__ S)
{
    extern __shared__ char smc[];
    uint32_t sb = smem_u32(smc);
    const uint32_t aoff[2] = { 0u, 24576u };
    const uint32_t boff[2] = { 8192u, 32768u };

    int tid = threadIdx.x, lane = tid & 31, wid = tid >> 5;
    int wm = wid & 1, wn = wid >> 1;          // 2 x 4 warps
    int z = blockIdx.z, bm = blockIdx.y * SBM, bn = blockIdx.x * SBN;
    const __nv_bfloat16* Az = Qs + (size_t)z * N_DAY * D;
    const __nv_bfloat16* Bz = Ks + (size_t)z * N_CELLS * D;

    float d[4][8][4];
    #pragma unroll
    for (int mt = 0; mt < 4; mt++)
        #pragma unroll
        for (int nt = 0; nt < 8; nt++)
            #pragma unroll
            for (int c = 0; c < 4; c++) d[mt][nt][c] = 0.f;

    int lr  = lane & 15;
    int lch = lane >> 4;

    auto load_stage = [&](int ks, int st) {
        int k0 = ks * 32;
        const __nv_bfloat16* Ag = Az + (size_t)bm * D + k0;
        const __nv_bfloat16* Bg = Bz + (size_t)bn * D + k0;
        #pragma unroll
        for (int j = 0; j < 2; j++) {
            int idx = tid + 256 * j;
            int r = idx >> 2, c = idx & 3;
            cp16(sb + aoff[st] + phys(r, c), Ag + (size_t)r * D + c * 8);
        }
        #pragma unroll
        for (int j = 0; j < 4; j++) {
            int idx = tid + 256 * j;
            int r = idx >> 2, c = idx & 3;
            cp16(sb + boff[st] + phys(r, c), Bg + (size_t)r * D + c * 8);
        }
    };

    load_stage(0, 0);
    CP_COMMIT();

    #pragma unroll 1
    for (int ks = 0; ks < NSTEP; ks++) {
        int st = ks & 1;
        if (ks < NSTEP - 1) { load_stage(ks + 1, st ^ 1); CP_COMMIT(); CP_WAIT(1); }
        else                { CP_WAIT(0); }
        __syncthreads();

        #pragma unroll
        for (int kk = 0; kk < 2; kk++) {
            uint32_t a[4][4];
            #pragma unroll
            for (int mt = 0; mt < 4; mt++) {
                int row = wm * 64 + mt * 16 + lr;
                int ch  = 2 * kk + lch;
                ldsm_x4(sb + aoff[st] + phys(row, ch), a[mt][0], a[mt][1], a[mt][2], a[mt][3]);
            }
            uint32_t b[8][2];
            #pragma unroll
            for (int gt = 0; gt < 4; gt++) {
                int row = wn * 64 + gt * 16 + lr;
                int ch  = 2 * kk + lch;
                uint32_t r0, r1, r2, r3;
                ldsm_x4(sb + boff[st] + phys(row, ch), r0, r1, r2, r3);
                b[2 * gt][0] = r0; b[2 * gt][1] = r2;
                b[2 * gt + 1][0] = r1; b[2 * gt + 1][1] = r3;
            }
            #pragma unroll
            for (int mt = 0; mt < 4; mt++)
                #pragma unroll
                for (int nt = 0; nt < 8; nt++)
                    mma_bf16(d[mt][nt], a[mt], b[nt]);
        }
        __syncthreads();
    }

    // Epilogue: stage 64-row half-tiles in smem (conflict-free), write coalesced 16B.
    const float scale = 0.0625f;
    __nv_bfloat16* Sz = S + (size_t)z * N_DAY * N_CELLS;
    uint32_t* su = (uint32_t*)smc;   // [64][132] uint32 = 33792 B
    #pragma unroll
    for (int p = 0; p < 2; p++) {
        if (wm == p) {
            #pragma unroll
            for (int mt = 0; mt < 4; mt++) {
                #pragma unroll
                for (int nt = 0; nt < 8; nt++) {
                    int r0 = mt * 16 + (lane >> 2);
                    int cu = wn * 32 + nt * 4 + (lane & 3);
                    __nv_bfloat162 v0 = __floats2bfloat162_rn(d[mt][nt][0] * scale, d[mt][nt][1] * scale);
                    __nv_bfloat162 v1 = __floats2bfloat162_rn(d[mt][nt][2] * scale, d[mt][nt][3] * scale);
                    su[r0 * 132 + cu]       = *(uint32_t*)&v0;
                    su[(r0 + 8) * 132 + cu] = *(uint32_t*)&v1;
                }
            }
        }
        __syncthreads();
        #pragma unroll
        for (int it = 0; it < 8; it++) {
            int idx = it * 256 + tid;
            int r = idx >> 5, q = idx & 31;
            uint4 v = *(uint4*)&su[r * 132 + q * 4];
            *(uint4*)(Sz + (size_t)(bm + p * 64 + r) * N_CELLS + bn + q * 8) = v;
        }
        __syncthreads();
    }
}

// ---------------- fused top-k + context (float4 rescore gather) ----------------
__global__ void __launch_bounds__(256) topk_ctx_kernel(
    const __nv_bfloat16* __restrict__ scores, const float* __restrict__ Qf,
    const float* __restrict__ Kf, const float* __restrict__ Mx,
    float* __restrict__ attn, float* __restrict__ idxo, float* __restrict__ ctx)
{
    __shared__ float qrow[D];
    __shared__ int   red[8];
    __shared__ int   sLo, sHi, sC;
    __shared__ int   buf[CAP];
    __shared__ float rv[CAP];
    __shared__ float vals[TOPK];
    __shared__ int   inds[TOPK];
    __shared__ float aw[TOPK];

    int row = blockIdx.x;
    int b = row >> 11;
    int tid = threadIdx.x;
    int lane = tid & 31, wid = tid >> 5;
    const __nv_bfloat16* sp = scores + (size_t)row * N_CELLS;

    qrow[tid] = Qf[(size_t)row * D + tid];
    if (tid == 0) { sLo = 0; sHi = 65536; sC = 0; }

    // load 32 bf16 scores per thread; convert in-register to packed monotonic 16-bit keys
    uint32_t kp[16];
    #pragma unroll
    for (int it = 0; it < 4; it++) {
        uint4 p = ((const uint4*)sp)[it * 256 + tid];
        uint32_t ww[4] = { p.x, p.y, p.z, p.w };
        #pragma unroll
        for (int h = 0; h < 4; h++) {
            uint32_t v = ww[h];
            uint32_t m = ((v >> 15) & 0x00010001u) * 0xFFFFu;
            kp[it * 4 + h] = v ^ (m | 0x80008000u);
        }
    }
    __syncthreads();

    // binary search: largest T with count(key >= T) >= NCAND
    int lo = 0, hi = 65536;
    #pragma unroll 1
    for (int iter = 0; iter < 16; iter++) {
        uint32_t T = (uint32_t)((lo + hi) >> 1);
        int cnt = 0;
        #pragma unroll
        for (int r = 0; r < 16; r++) {
            cnt += ((kp[r] & 0xFFFFu) >= T);
            cnt += ((kp[r] >> 16) >= T);
        }
        #pragma unroll
        for (int off = 16; off; off >>= 1) cnt += __shfl_xor_sync(0xffffffffu, cnt, off);
        if (lane == 0) red[wid] = cnt;
        __syncthreads();
        if (tid == 0) {
            int c = 0;
            #pragma unroll
            for (int w = 0; w < 8; w++) c += red[w];
            if (c >= NCAND) sLo = (int)T; else sHi = (int)T;
        }
        __syncthreads();
        lo = sLo; hi = sHi;
    }
    uint32_t Tstar = (uint32_t)lo;

    // collection: ballot-compacted indices with key >= Tstar
    #pragma unroll
    for (int it = 0; it < 4; it++) {
        int base = (it * 256 + tid) * 8;
        #pragma unroll
        for (int h = 0; h < 4; h++) {
            uint32_t k2 = kp[it * 4 + h];
            #pragma unroll
            for (int s = 0; s < 2; s++) {
                uint32_t key = (s == 0) ? (k2 & 0xFFFFu) : (k2 >> 16);
                bool hit = key >= Tstar;
                uint32_t bal = __ballot_sync(0xffffffffu, hit);
                if (bal) {
                    int ldr = (int)(__ffs(bal) - 1);
                    int wbase = 0;
                    if (lane == ldr) wbase = atomicAdd(&sC, __popc(bal));
                    wbase = __shfl_sync(0xffffffffu, wbase, ldr);
                    if (hit) {
                        int pos = wbase + __popc(bal & ((1u << lane) - 1u));
                        if (pos < CAP) buf[pos] = base + h * 2 + s;
                    }
                }
            }
        }
    }
    __syncthreads();
    int C = sC < CAP ? sC : CAP;

    // fp32 rescore: serial k-order fmaf chain via float4 loads (bit-identical order,
    // 4x fewer L1 load instructions than scalar)
    for (int i = tid; i < C; i += 256) {
        const float4* kr = (const float4*)(Kf + (size_t)b * N_CELLS * D + (size_t)buf[i] * D);
        const float4* qr = (const float4*)qrow;
        float s = 0.f;
        #pragma unroll 8
        for (int k = 0; k < D / 4; k++) {
            float4 kv = kr[k];
            float4 qv = qr[k];
            s = fmaf(qv.x, kv.x, s);
            s = fmaf(qv.y, kv.y, s);
            s = fmaf(qv.z, kv.z, s);
            s = fmaf(qv.w, kv.w, s);
        }
        rv[i] = s * 0.0625f;
    }
    __syncthreads();

    // warp 0: select top-32 by (value desc, index asc), softmax, write
    if (tid < 32) {
        for (int it = 0; it < TOPK; it++) {
            float v = -INFINITY; int ci = 1 << 30; int slot = 0;
            for (int j = tid; j < C; j += 32) {
                float x = rv[j]; int cj = buf[j];
                if (x > v || (x == v && cj < ci)) { v = x; ci = cj; slot = j; }
            }
            #pragma unroll
            for (int off = 16; off; off >>= 1) {
                float ov = __shfl_down_sync(0xffffffffu, v, off);
                int   oc = __shfl_down_sync(0xffffffffu, ci, off);
                int   os = __shfl_down_sync(0xffffffffu, slot, off);
                if (ov > v || (ov == v && oc < ci)) { v = ov; ci = oc; slot = os; }
            }
            v    = __shfl_sync(0xffffffffu, v, 0);
            ci   = __shfl_sync(0xffffffffu, ci, 0);
            slot = __shfl_sync(0xffffffffu, slot, 0);
            if (tid == 0) { vals[it] = v; inds[it] = ci; rv[slot] = -INFINITY; }
            __syncwarp();
        }
        float m = vals[0];
        float e = expf(vals[tid] - m);
        float s = e;
        #pragma unroll
        for (int off = 16; off; off >>= 1) s += __shfl_xor_sync(0xffffffffu, s, off);
        float w = e / s;
        aw[tid] = w;
        attn[(size_t)row * TOPK + tid] = w;
        idxo[(size_t)row * TOPK + tid] = (float)inds[tid];
    }
    __syncthreads();

    // fused context: m_ctx[row,:] = sum_k aw[k] * macro[b, inds[k], :]  (coalesced)
    {
        const float* Mb = Mx + (size_t)b * N_CELLS * D;
        float acc = 0.f;
        #pragma unroll 8
        for (int k = 0; k < TOPK; k++)
            acc = fmaf(aw[k], Mb[(size_t)inds[k] * D + tid], acc);
        ctx[(size_t)row * D + tid] = acc;
    }
}

// ---------------- launch ----------------
extern "C" void kernel_launch(void* const* d_in, const int* in_sizes, int n_in,
                              void* d_out, int out_size)
{
    const float* micro = (const float*)d_in[0];
    const float* macro = (const float*)d_in[1];
    const float* mp_w  = (const float*)d_in[2];
    const float* mp_b  = (const float*)d_in[3];
    const float* wq    = (const float*)d_in[4];
    const float* wk    = (const float*)d_in[5];
    const float* wv    = (const float*)d_in[6];
    const float* op_w  = (const float*)d_in[7];
    const float* op_b  = (const float*)d_in[8];

    float* out  = (float*)d_out;
    float* attn = out + (size_t)ROWS_Q * D;
    float* idxo = attn + (size_t)ROWS_Q * TOPK;

    float *p_xm, *p_q, *p_k, *p_mc, *p_w2;
    __nv_bfloat16 *p_qs, *p_ks, *p_s;
    cudaGetSymbolAddress((void**)&p_xm, g_xmicro);
    cudaGetSymbolAddress((void**)&p_q,  g_q);
    cudaGetSymbolAddress((void**)&p_k,  g_k);
    cudaGetSymbolAddress((void**)&p_mc, g_mctx);
    cudaGetSymbolAddress((void**)&p_w2, g_w2);
    cudaGetSymbolAddress((void**)&p_qs, g_qs);
    cudaGetSymbolAddress((void**)&p_ks, g_ks);
    cudaGetSymbolAddress((void**)&p_s,  g_sbf);

    cudaFuncSetAttribute(scores_mma_kernel,
                         cudaFuncAttributeMaxDynamicSharedMemorySize, SMEM_MMA);

    // 0. x_micro = micro @ mp_w + mp_b
    micro_proj_kernel<<<ROWS_Q / 8, 256>>>(micro, mp_w, mp_b, p_xm);

    // 1. fused Q + K projections (fp32 + bf16 shadows)
    qk_proj_kernel<<<dim3(D / BN, QBLKS + ROWS_M / BM), 256>>>(
        p_xm, macro, wq, wk, p_q, p_k, p_qs, p_ks);

    // 2. approx scores = scale * Qb @ Kb^T  (tensor cores)
    scores_mma_kernel<<<dim3(N_CELLS / SBN, N_DAY / SBM, BATCH), 256, SMEM_MMA>>>(p_qs, p_ks, p_s);

    // 3. top-k + context, float4 rescore  [ncu capture slot]
    topk_ctx_kernel<<<ROWS_Q, 256>>>(p_s, p_q, p_k, macro, attn, idxo, p_mc);

    // 4. W2 = wv @ op_w
    small_gemm_kernel<<<D, 256>>>(wv, op_w, p_w2);

    // 5. x_conditioned = x_micro + m_ctx @ W2 + op_b
    out_gemm_kernel<<<dim3(D / BN, ROWS_Q / BM), 256>>>(p_mc, p_w2, out, p_xm, op_b);

    (void)in_sizes; (void)n_in; (void)out_size;
}